// round 8
// baseline (speedup 1.0000x reference)
#include <cuda_runtime.h>

#define N_IN       1024
#define BATCH      1024
#define DEG        32
#define TOTAL_COLS 18432
#define N_TANH     17408          // neuron columns (cols N_IN..TOTAL_COLS-1)
#define OUT_COL_BASE 17408
#define QSCALE 5818.0f            // 32000 / 5.5 ; |X|<=5.5 w.h.p., saturating
#define QINV   (1.0f / 5818.0f)

// Unified int16 Q buffer, column-major: cols 0..1023 quantized input,
// cols 1024..18431 tanh outputs. 37.7 MB.
__device__ short g_q[(size_t)TOTAL_COLS * BATCH];
// Per-neuron-column ready flags + global work counter.
__device__ int g_flag[N_TANH];
__device__ unsigned g_next;

// ---------------------------------------------------------------------------
__global__ void init_kernel() {
    int i = blockIdx.x * 256 + threadIdx.x;
    if (i == 0) g_next = 0u;
    for (; i < N_TANH; i += gridDim.x * 256) g_flag[i] = 0;
}

// ---------------------------------------------------------------------------
// Transpose X (BATCH x N_IN row-major fp32) -> g_q cols 0..1023 (int16, sat).
// ---------------------------------------------------------------------------
__global__ void transpose_in_kernel(const float* __restrict__ X) {
    __shared__ float tile[32][33];
    int bx = blockIdx.x * 32, by = blockIdx.y * 32;
    int tx = threadIdx.x, ty = threadIdx.y;
    #pragma unroll
    for (int i = 0; i < 32; i += 8)
        tile[ty + i][tx] = X[(by + ty + i) * N_IN + (bx + tx)];
    __syncthreads();
    #pragma unroll
    for (int i = 0; i < 32; i += 8) {
        int q = __float2int_rn(tile[tx][ty + i] * QSCALE);
        q = max(-32767, min(32767, q));
        g_q[(size_t)(bx + ty + i) * BATCH + (by + tx)] = (short)q;
    }
}

// ---------------------------------------------------------------------------
// Persistent dataflow kernel: blocks claim neurons (global index order ==
// layer order). Per-column ready flags replace layer barriers, so layer L+1
// work backfills layer L's scheduling tail. 128 threads, 8 batch elems each,
// DP2A exact int16 accumulation (proven R6 gather core).
// ---------------------------------------------------------------------------
__global__ void __launch_bounds__(128) net_kernel(
    const int* __restrict__ child_idx, const float* __restrict__ w_ptr)
{
    const int t = threadIdx.x;
    __shared__ int      sidx[DEG];
    __shared__ unsigned s_item;

    const uint4* q4 = reinterpret_cast<const uint4*>(g_q);
    const float  w  = __ldg(w_ptr);
    const float  ws = w * QINV;

    for (;;) {
        __syncthreads();                    // protect s_item / sidx reuse
        if (t == 0) s_item = atomicAdd(&g_next, 1u);
        __syncthreads();
        const unsigned item = s_item;
        if (item >= (unsigned)N_TANH) return;

        // Load child indices; poll readiness of non-input children.
        if (t < DEG) {
            int idx = child_idx[item * DEG + t];
            sidx[t] = idx;
            if (idx >= N_IN) {
                volatile int* f = &g_flag[idx - N_IN];
                while (*f == 0) { __nanosleep(128); }
            }
        }
        __syncthreads();
        __threadfence();                    // acquire: data after observed flags

        int a0=0,a1=0,a2=0,a3=0,a4=0,a5=0,a6=0,a7=0;
        #pragma unroll
        for (int k = 0; k < DEG; k++) {
            uint4 v = q4[(size_t)sidx[k] * (BATCH / 8) + t];
            a0 = __dp2a_lo((int)v.x, 0x0001, a0);
            a1 = __dp2a_lo((int)v.x, 0x0100, a1);
            a2 = __dp2a_lo((int)v.y, 0x0001, a2);
            a3 = __dp2a_lo((int)v.y, 0x0100, a3);
            a4 = __dp2a_lo((int)v.z, 0x0001, a4);
            a5 = __dp2a_lo((int)v.z, 0x0100, a5);
            a6 = __dp2a_lo((int)v.w, 0x0001, a6);
            a7 = __dp2a_lo((int)v.w, 0x0100, a7);
        }

        int q0 = __float2int_rn(tanhf(ws * (float)a0) * QSCALE);
        int q1 = __float2int_rn(tanhf(ws * (float)a1) * QSCALE);
        int q2 = __float2int_rn(tanhf(ws * (float)a2) * QSCALE);
        int q3 = __float2int_rn(tanhf(ws * (float)a3) * QSCALE);
        int q4_= __float2int_rn(tanhf(ws * (float)a4) * QSCALE);
        int q5 = __float2int_rn(tanhf(ws * (float)a5) * QSCALE);
        int q6 = __float2int_rn(tanhf(ws * (float)a6) * QSCALE);
        int q7 = __float2int_rn(tanhf(ws * (float)a7) * QSCALE);

        uint4 o;
        o.x = (q0 & 0xFFFF) | (q1 << 16);
        o.y = (q2 & 0xFFFF) | (q3 << 16);
        o.z = (q4_& 0xFFFF) | (q5 << 16);
        o.w = (q6 & 0xFFFF) | (q7 << 16);
        reinterpret_cast<uint4*>(g_q)[(size_t)(N_IN + item) * (BATCH / 8) + t] = o;

        // Publish: all threads' stores globally visible, then set flag.
        __threadfence();
        __syncthreads();
        if (t == 0) *((volatile int*)&g_flag[item]) = 1;
    }
}

// ---------------------------------------------------------------------------
// Transpose last 1024 cols of g_q -> out (BATCH x 1024 fp32), dequantized.
// ---------------------------------------------------------------------------
__global__ void transpose_out_kernel(float* __restrict__ out) {
    __shared__ float tile[32][33];
    int b0 = blockIdx.x * 32, c0 = blockIdx.y * 32;
    int tx = threadIdx.x, ty = threadIdx.y;
    #pragma unroll
    for (int i = 0; i < 32; i += 8)
        tile[ty + i][tx] = (float)
            g_q[(size_t)(OUT_COL_BASE + c0 + ty + i) * BATCH + (b0 + tx)]
            * QINV;
    __syncthreads();
    #pragma unroll
    for (int i = 0; i < 32; i += 8)
        out[(size_t)(b0 + ty + i) * 1024 + (c0 + tx)] = tile[tx][ty + i];
}

// ---------------------------------------------------------------------------
extern "C" void kernel_launch(void* const* d_in, const int* in_sizes, int n_in,
                              void* d_out, int out_size) {
    const float* X         = (const float*)d_in[0];
    const float* w         = (const float*)d_in[1];
    const int*   child_idx = (const int*)d_in[2];
    float*       out       = (float*)d_out;
    (void)in_sizes; (void)n_in; (void)out_size;

    dim3 tgrid(32, 32), tblock(32, 8);

    init_kernel<<<68, 256>>>();
    transpose_in_kernel<<<tgrid, tblock>>>(X);

    // Persistent grid: guaranteed co-resident (no oversubscription -> no
    // deadlock on flag polls).
    int dev = 0;
    cudaGetDevice(&dev);
    int sms = 0;
    cudaDeviceGetAttribute(&sms, cudaDevAttrMultiProcessorCount, dev);
    int per_sm = 0;
    cudaOccupancyMaxActiveBlocksPerMultiprocessor(&per_sm, net_kernel, 128, 0);
    if (per_sm < 1) per_sm = 1;
    unsigned grid = (unsigned)(sms * per_sm);
    if (grid > (unsigned)N_TANH) grid = N_TANH;

    net_kernel<<<grid, 128>>>(child_idx, w);

    transpose_out_kernel<<<tgrid, tblock>>>(out);
}

// round 9
// speedup vs baseline: 1.4853x; 1.4853x over previous
#include <cuda_runtime.h>

#define N_IN       1024
#define BATCH      1024
#define DEG        32
#define N_LAYERS   9
#define TOTAL_COLS 18432
#define N_OUT      1024

// Unified int16 Q buffer, column-major: cols 0..1023 quantized input,
// cols 1024..18431 tanh outputs. Single dynamic scale g_s. 37.7 MB.
// (Layer 9's columns are never gathered, so they are never written here.)
__device__ short g_q[(size_t)TOTAL_COLS * BATCH];
// Dynamic quantization scale state
__device__ unsigned g_maxbits;
__device__ float g_s, g_is;

__global__ void init_kernel() { g_maxbits = 0u; }

__global__ void maxabs_kernel(const float* __restrict__ X) {
    const float4* X4 = reinterpret_cast<const float4*>(X);
    float m = 0.f;
    for (int i = blockIdx.x * 256 + threadIdx.x; i < (N_IN * BATCH) / 4;
         i += gridDim.x * 256) {
        float4 v = X4[i];
        m = fmaxf(m, fmaxf(fmaxf(fabsf(v.x), fabsf(v.y)),
                           fmaxf(fabsf(v.z), fabsf(v.w))));
    }
    #pragma unroll
    for (int o = 16; o; o >>= 1)
        m = fmaxf(m, __shfl_xor_sync(0xFFFFFFFFu, m, o));
    if ((threadIdx.x & 31) == 0)
        atomicMax(&g_maxbits, __float_as_uint(m));  // non-neg floats: bit order = value order
}

__global__ void scale_kernel() {
    float m = __uint_as_float(g_maxbits);
    if (m < 1.0f) m = 1.0f;          // tanh outputs (|v|<1) must also fit
    float s = 32000.0f / m;
    g_s = s;
    g_is = 1.0f / s;
}

// ---------------------------------------------------------------------------
// Transpose X (BATCH x N_IN row-major fp32) -> g_q cols 0..1023 (int16).
// ---------------------------------------------------------------------------
__global__ void transpose_in_kernel(const float* __restrict__ X) {
    __shared__ float tile[32][33];
    int bx = blockIdx.x * 32, by = blockIdx.y * 32;
    int tx = threadIdx.x, ty = threadIdx.y;
    #pragma unroll
    for (int i = 0; i < 32; i += 8)
        tile[ty + i][tx] = X[(by + ty + i) * N_IN + (bx + tx)];
    __syncthreads();
    const float s = g_s;
    #pragma unroll
    for (int i = 0; i < 32; i += 8)
        g_q[(size_t)(bx + ty + i) * BATCH + (by + tx)] =
            (short)__float2int_rn(tile[tx][ty + i] * s);
}

// ---------------------------------------------------------------------------
// Shared gather core: 128 threads, thread t owns batch elems 8t..8t+7
// (one uint4 = 8 int16). Exact integer accumulation via DP2A.
// ---------------------------------------------------------------------------
__device__ __forceinline__ void gather_sum(const int* __restrict__ sidx, int t,
                                           int acc[8]) {
    const uint4* q4 = reinterpret_cast<const uint4*>(g_q);
    int a0=0,a1=0,a2=0,a3=0,a4=0,a5=0,a6=0,a7=0;
    #pragma unroll
    for (int k = 0; k < DEG; k++) {
        uint4 v = q4[(size_t)sidx[k] * (BATCH / 8) + t];
        a0 = __dp2a_lo((int)v.x, 0x0001, a0);  // low  int16
        a1 = __dp2a_lo((int)v.x, 0x0100, a1);  // high int16
        a2 = __dp2a_lo((int)v.y, 0x0001, a2);
        a3 = __dp2a_lo((int)v.y, 0x0100, a3);
        a4 = __dp2a_lo((int)v.z, 0x0001, a4);
        a5 = __dp2a_lo((int)v.z, 0x0100, a5);
        a6 = __dp2a_lo((int)v.w, 0x0001, a6);
        a7 = __dp2a_lo((int)v.w, 0x0100, a7);
    }
    acc[0]=a0; acc[1]=a1; acc[2]=a2; acc[3]=a3;
    acc[4]=a4; acc[5]=a5; acc[6]=a6; acc[7]=a7;
}

// ---------------------------------------------------------------------------
// Layers 1..8: block j computes neuron (col_base + j), writes quantized column.
// ---------------------------------------------------------------------------
__global__ void __launch_bounds__(128) layer_kernel(
    const int* __restrict__ child_idx, const float* __restrict__ w_ptr,
    int col_base)
{
    const int j = blockIdx.x, t = threadIdx.x;
    __shared__ int sidx[DEG];
    if (t < DEG) sidx[t] = child_idx[j * DEG + t];
    __syncthreads();

    int a[8];
    gather_sum(sidx, t, a);

    const float w = __ldg(w_ptr), is = g_is, s = g_s;
    const float ws = w * is;

    int q[8];
    #pragma unroll
    for (int i = 0; i < 8; i++)
        q[i] = __float2int_rn(tanhf(ws * (float)a[i]) * s);

    uint4 o;
    o.x = (q[0] & 0xFFFF) | (q[1] << 16);
    o.y = (q[2] & 0xFFFF) | (q[3] << 16);
    o.z = (q[4] & 0xFFFF) | (q[5] << 16);
    o.w = (q[6] & 0xFFFF) | (q[7] << 16);
    reinterpret_cast<uint4*>(g_q)[(size_t)(col_base + j) * (BATCH / 8) + t] = o;
}

// ---------------------------------------------------------------------------
// Layer 9 (final): outputs are never gathered by later layers, so write fp32
// results straight into d_out (row-major) — removes the quantized column
// write, its re-read, and the entire transpose_out kernel.
// Block j = output column j; thread t stores out[8t+i][j], i=0..7.
// ---------------------------------------------------------------------------
__global__ void __launch_bounds__(128) last_layer_kernel(
    const int* __restrict__ child_idx, const float* __restrict__ w_ptr,
    float* __restrict__ out)
{
    const int j = blockIdx.x, t = threadIdx.x;
    __shared__ int sidx[DEG];
    if (t < DEG) sidx[t] = child_idx[j * DEG + t];
    __syncthreads();

    int a[8];
    gather_sum(sidx, t, a);

    const float w = __ldg(w_ptr), is = g_is;
    const float ws = w * is;

    #pragma unroll
    for (int i = 0; i < 8; i++)
        out[(size_t)(8 * t + i) * N_OUT + j] = tanhf(ws * (float)a[i]);
}

// ---------------------------------------------------------------------------
extern "C" void kernel_launch(void* const* d_in, const int* in_sizes, int n_in,
                              void* d_out, int out_size) {
    const float* X         = (const float*)d_in[0];
    const float* w         = (const float*)d_in[1];
    const int*   child_idx = (const int*)d_in[2];
    float*       out       = (float*)d_out;
    (void)in_sizes; (void)n_in; (void)out_size;

    dim3 tgrid(32, 32), tblock(32, 8);

    init_kernel<<<1, 1>>>();
    maxabs_kernel<<<64, 256>>>(X);
    scale_kernel<<<1, 1>>>();
    transpose_in_kernel<<<tgrid, tblock>>>(X);

    // Layers 1..8 write quantized columns; layer 9 writes d_out directly.
    int idx_base = 0;
    int col_base = N_IN;
    for (int li = 0; li < 8; li++) {
        layer_kernel<<<2048, 128>>>(child_idx + (size_t)idx_base * DEG, w, col_base);
        idx_base += 2048;
        col_base += 2048;
    }
    last_layer_kernel<<<1024, 128>>>(child_idx + (size_t)idx_base * DEG, w, out);
}

// round 10
// speedup vs baseline: 1.5861x; 1.0679x over previous
#include <cuda_runtime.h>

#define N_IN       1024
#define BATCH      1024
#define DEG        32
#define TOTAL_COLS 18432
#define N_OUT      1024

// Unified int16 Q buffer, column-major: cols 0..1023 quantized input,
// cols 1024.. tanh outputs. Single dynamic scale g_s. 37.7 MB.
__device__ short g_q[(size_t)TOTAL_COLS * BATCH];
__device__ unsigned g_maxbits;
__device__ float g_s, g_is;

// PDL intrinsics (sm_90+)
__device__ __forceinline__ void pdl_wait() {
    asm volatile("griddepcontrol.wait;" ::: "memory");
}
__device__ __forceinline__ void pdl_launch_dependents() {
    asm volatile("griddepcontrol.launch_dependents;" ::: "memory");
}

__global__ void init_kernel() { g_maxbits = 0u; }

__global__ void maxabs_kernel(const float* __restrict__ X) {
    const float4* X4 = reinterpret_cast<const float4*>(X);
    float m = 0.f;
    for (int i = blockIdx.x * 256 + threadIdx.x; i < (N_IN * BATCH) / 4;
         i += gridDim.x * 256) {
        float4 v = X4[i];
        m = fmaxf(m, fmaxf(fmaxf(fabsf(v.x), fabsf(v.y)),
                           fmaxf(fabsf(v.z), fabsf(v.w))));
    }
    #pragma unroll
    for (int o = 16; o; o >>= 1)
        m = fmaxf(m, __shfl_xor_sync(0xFFFFFFFFu, m, o));
    if ((threadIdx.x & 31) == 0)
        atomicMax(&g_maxbits, __float_as_uint(m));  // non-neg floats: bit order = value order
}

__global__ void scale_kernel() {
    float m = __uint_as_float(g_maxbits);
    if (m < 1.0f) m = 1.0f;          // tanh outputs (|v|<1) must also fit
    float s = 32000.0f / m;
    g_s = s;
    g_is = 1.0f / s;
}

// ---------------------------------------------------------------------------
// Transpose X -> g_q cols 0..1023 (int16). PDL: X read overlaps scale tail;
// g_s read only after wait. Signals dependents after stores.
// ---------------------------------------------------------------------------
__global__ void transpose_in_kernel(const float* __restrict__ X) {
    __shared__ float tile[32][33];
    int bx = blockIdx.x * 32, by = blockIdx.y * 32;
    int tx = threadIdx.x, ty = threadIdx.y;
    #pragma unroll
    for (int i = 0; i < 32; i += 8)
        tile[ty + i][tx] = X[(by + ty + i) * N_IN + (bx + tx)];
    __syncthreads();
    pdl_wait();                       // g_s valid after scale_kernel completes
    const float s = g_s;
    #pragma unroll
    for (int i = 0; i < 32; i += 8)
        g_q[(size_t)(bx + ty + i) * BATCH + (by + tx)] =
            (short)__float2int_rn(tile[tx][ty + i] * s);
    pdl_launch_dependents();
}

// ---------------------------------------------------------------------------
// Gather core: 128 threads, thread t owns batch elems 8t..8t+7 (one uint4 =
// 8 int16). Exact integer accumulation via DP2A.
// ---------------------------------------------------------------------------
__device__ __forceinline__ void gather_sum(const int* __restrict__ sidx, int t,
                                           int acc[8]) {
    const uint4* q4 = reinterpret_cast<const uint4*>(g_q);
    int a0=0,a1=0,a2=0,a3=0,a4=0,a5=0,a6=0,a7=0;
    #pragma unroll
    for (int k = 0; k < DEG; k++) {
        uint4 v = q4[(size_t)sidx[k] * (BATCH / 8) + t];
        a0 = __dp2a_lo((int)v.x, 0x0001, a0);
        a1 = __dp2a_lo((int)v.x, 0x0100, a1);
        a2 = __dp2a_lo((int)v.y, 0x0001, a2);
        a3 = __dp2a_lo((int)v.y, 0x0100, a3);
        a4 = __dp2a_lo((int)v.z, 0x0001, a4);
        a5 = __dp2a_lo((int)v.z, 0x0100, a5);
        a6 = __dp2a_lo((int)v.w, 0x0001, a6);
        a7 = __dp2a_lo((int)v.w, 0x0100, a7);
    }
    acc[0]=a0; acc[1]=a1; acc[2]=a2; acc[3]=a3;
    acc[4]=a4; acc[5]=a5; acc[6]=a6; acc[7]=a7;
}

// ---------------------------------------------------------------------------
// Layers 1..8: preamble (index load) overlaps predecessor tail via PDL;
// dependents released right after the column store.
// ---------------------------------------------------------------------------
__global__ void __launch_bounds__(128) layer_kernel(
    const int* __restrict__ child_idx, const float* __restrict__ w_ptr,
    int col_base)
{
    const int j = blockIdx.x, t = threadIdx.x;
    __shared__ int sidx[DEG];
    if (t < DEG) sidx[t] = child_idx[j * DEG + t];   // input-only: pre-wait OK
    __syncthreads();
    pdl_wait();                        // predecessor's g_q writes now visible

    int a[8];
    gather_sum(sidx, t, a);

    const float w = __ldg(w_ptr), is = g_is, s = g_s;
    const float ws = w * is;

    int q[8];
    #pragma unroll
    for (int i = 0; i < 8; i++)
        q[i] = __float2int_rn(tanhf(ws * (float)a[i]) * s);

    uint4 o;
    o.x = (q[0] & 0xFFFF) | (q[1] << 16);
    o.y = (q[2] & 0xFFFF) | (q[3] << 16);
    o.z = (q[4] & 0xFFFF) | (q[5] << 16);
    o.w = (q[6] & 0xFFFF) | (q[7] << 16);
    reinterpret_cast<uint4*>(g_q)[(size_t)(col_base + j) * (BATCH / 8) + t] = o;

    pdl_launch_dependents();           // release next layer before block exit
}

// ---------------------------------------------------------------------------
// Layer 9: outputs never gathered -> write fp32 straight to d_out (row-major).
// ---------------------------------------------------------------------------
__global__ void __launch_bounds__(128) last_layer_kernel(
    const int* __restrict__ child_idx, const float* __restrict__ w_ptr,
    float* __restrict__ out)
{
    const int j = blockIdx.x, t = threadIdx.x;
    __shared__ int sidx[DEG];
    if (t < DEG) sidx[t] = child_idx[j * DEG + t];
    __syncthreads();
    pdl_wait();

    int a[8];
    gather_sum(sidx, t, a);

    const float w = __ldg(w_ptr), is = g_is;
    const float ws = w * is;

    #pragma unroll
    for (int i = 0; i < 8; i++)
        out[(size_t)(8 * t + i) * N_OUT + j] = tanhf(ws * (float)a[i]);
}

// ---------------------------------------------------------------------------
// Host-side PDL launch helper.
// ---------------------------------------------------------------------------
template <typename... Args>
static void launch_pdl(void (*kern)(Args...), dim3 grid, dim3 block,
                       Args... args) {
    cudaLaunchConfig_t cfg = {};
    cfg.gridDim = grid;
    cfg.blockDim = block;
    cfg.dynamicSmemBytes = 0;
    cfg.stream = 0;
    cudaLaunchAttribute attr[1];
    attr[0].id = cudaLaunchAttributeProgrammaticStreamSerialization;
    attr[0].val.programmaticStreamSerializationAllowed = 1;
    cfg.attrs = attr;
    cfg.numAttrs = 1;
    cudaLaunchKernelEx(&cfg, kern, args...);
}

extern "C" void kernel_launch(void* const* d_in, const int* in_sizes, int n_in,
                              void* d_out, int out_size) {
    const float* X         = (const float*)d_in[0];
    const float* w         = (const float*)d_in[1];
    const int*   child_idx = (const int*)d_in[2];
    float*       out       = (float*)d_out;
    (void)in_sizes; (void)n_in; (void)out_size;

    init_kernel<<<1, 1>>>();
    maxabs_kernel<<<64, 256>>>(X);
    scale_kernel<<<1, 1>>>();

    launch_pdl(transpose_in_kernel, dim3(32, 32), dim3(32, 8), X);

    int idx_base = 0;
    int col_base = N_IN;
    for (int li = 0; li < 8; li++) {
        launch_pdl(layer_kernel, dim3(2048), dim3(128),
                   (const int*)(child_idx + (size_t)idx_base * DEG), w, col_base);
        idx_base += 2048;
        col_base += 2048;
    }
    launch_pdl(last_layer_kernel, dim3(1024), dim3(128),
               (const int*)(child_idx + (size_t)idx_base * DEG), w, out);
}